// round 3
// baseline (speedup 1.0000x reference)
#include <cuda_runtime.h>
#include <math.h>
#include <stdint.h>

// Problem constants
#define B_   16
#define C_   384
#define N_   1024
#define NH   8
#define HD   48
#define HID  1536
#define M_   (B_*N_)     // 16384 tokens
#define QKVC (3*C_)      // 1152

// ---------------------------------------------------------------------------
// Scratch (static __device__ — no allocation allowed)
// ---------------------------------------------------------------------------
__device__ float g_xf [M_*C_];     // tokens (B,N,C)
__device__ float g_h  [M_*C_];     // LN output / final y (reused)
__device__ float g_qkv[M_*QKVC];   // qkv projections
__device__ float g_att[M_*C_];     // attention output
__device__ float g_x2 [M_*C_];     // residual after attention
__device__ float g_mid[M_*HID];    // FFN hidden

// ---------------------------------------------------------------------------
// Transpose: in (batch, rows, cols) -> out (batch, cols, rows)
// ---------------------------------------------------------------------------
__global__ void transpose_k(const float* __restrict__ in, float* __restrict__ out,
                            int rows, int cols) {
    __shared__ float t[32][33];
    int b = blockIdx.z;
    const float* ib = in  + (size_t)b * rows * cols;
    float*       ob = out + (size_t)b * rows * cols;
    int r = blockIdx.y * 32 + threadIdx.y;
    int c = blockIdx.x * 32 + threadIdx.x;
    t[threadIdx.y][threadIdx.x] = ib[(size_t)r * cols + c];
    __syncthreads();
    int oc = blockIdx.x * 32 + threadIdx.y;
    int orr = blockIdx.y * 32 + threadIdx.x;
    ob[(size_t)oc * rows + orr] = t[threadIdx.x][threadIdx.y];
}

// ---------------------------------------------------------------------------
// LayerNorm over rows of length 384.  grid: M_ blocks, block: 128 threads
// ---------------------------------------------------------------------------
__global__ void ln_k(const float* __restrict__ X, const float* __restrict__ w,
                     const float* __restrict__ bias, float* __restrict__ Y) {
    int row = blockIdx.x;
    int tid = threadIdx.x;
    const float* xr = X + (size_t)row * C_;
    float v0 = xr[tid], v1 = xr[tid + 128], v2 = xr[tid + 256];
    float s = v0 + v1 + v2;
    float q = v0 * v0 + v1 * v1 + v2 * v2;
    #pragma unroll
    for (int o = 16; o > 0; o >>= 1) {
        s += __shfl_xor_sync(0xffffffffu, s, o);
        q += __shfl_xor_sync(0xffffffffu, q, o);
    }
    __shared__ float ss[4], sq[4];
    int wid = tid >> 5, lane = tid & 31;
    if (lane == 0) { ss[wid] = s; sq[wid] = q; }
    __syncthreads();
    s = ss[0] + ss[1] + ss[2] + ss[3];
    q = sq[0] + sq[1] + sq[2] + sq[3];
    float mean = s * (1.0f / C_);
    float var  = q * (1.0f / C_) - mean * mean;
    float rstd = rsqrtf(var + 1e-5f);
    float* yr = Y + (size_t)row * C_;
    yr[tid]       = (v0 - mean) * rstd * w[tid]       + bias[tid];
    yr[tid + 128] = (v1 - mean) * rstd * w[tid + 128] + bias[tid + 128];
    yr[tid + 256] = (v2 - mean) * rstd * w[tid + 256] + bias[tid + 256];
}

// ---------------------------------------------------------------------------
// TF32 tensor-core NT GEMM: C[M,N] = A[M,K] * B[N,K]^T + bias[N]
// tile 128x128x32, 256 threads (8 warps, 4 in M x 2 in N), warp tile 32x64.
// mma.sync.aligned.m16n8k8 tf32. ACT: 1=exact GELU. RES: add residual.
// ---------------------------------------------------------------------------
__device__ __forceinline__ uint32_t f2tf32(float f) {
    uint32_t o;
    asm("cvt.rna.tf32.f32 %0, %1;" : "=r"(o) : "f"(f));
    return o;
}

#define AS_STRIDE 129

template<int ACT, int RES>
__global__ __launch_bounds__(256)
void gemm_tf32(const float* __restrict__ A, const float* __restrict__ B,
               const float* __restrict__ bias, const float* __restrict__ Res,
               float* __restrict__ C, int M, int N, int K) {
    __shared__ uint32_t As[32][AS_STRIDE];   // [k][m], tf32 bits
    __shared__ uint32_t Bs[32][AS_STRIDE];   // [k][n]

    const int tid  = threadIdx.x;
    const int lane = tid & 31;
    const int warp = tid >> 5;
    const int wm = (warp & 3) * 32;      // warp M offset in tile
    const int wn = (warp >> 2) * 64;     // warp N offset in tile
    const int m0 = blockIdx.y * 128;
    const int n0 = blockIdx.x * 128;

    float acc[2][8][4];
    #pragma unroll
    for (int i = 0; i < 2; i++)
        #pragma unroll
        for (int j = 0; j < 8; j++)
            #pragma unroll
            for (int c = 0; c < 4; c++) acc[i][j][c] = 0.0f;

    const int lr = tid >> 3;         // 0..31 : row within tile chunk
    const int lk = (tid & 7) * 4;    // k offset (float4)

    for (int k0 = 0; k0 < K; k0 += 32) {
        __syncthreads();
        #pragma unroll
        for (int hh = 0; hh < 4; hh++) {
            int r = lr + hh * 32;
            float4 va = *(const float4*)&A[(size_t)(m0 + r) * K + k0 + lk];
            As[lk + 0][r] = f2tf32(va.x); As[lk + 1][r] = f2tf32(va.y);
            As[lk + 2][r] = f2tf32(va.z); As[lk + 3][r] = f2tf32(va.w);
            float4 vb = *(const float4*)&B[(size_t)(n0 + r) * K + k0 + lk];
            Bs[lk + 0][r] = f2tf32(vb.x); Bs[lk + 1][r] = f2tf32(vb.y);
            Bs[lk + 2][r] = f2tf32(vb.z); Bs[lk + 3][r] = f2tf32(vb.w);
        }
        __syncthreads();

        #pragma unroll
        for (int kk = 0; kk < 32; kk += 8) {
            const int kq  = kk + (lane & 3);      // lane%4
            const int rq  = lane >> 2;            // lane/4
            uint32_t a[2][4];
            #pragma unroll
            for (int i = 0; i < 2; i++) {
                int rb = wm + i * 16 + rq;
                a[i][0] = As[kq    ][rb];
                a[i][1] = As[kq    ][rb + 8];
                a[i][2] = As[kq + 4][rb];
                a[i][3] = As[kq + 4][rb + 8];
            }
            #pragma unroll
            for (int j = 0; j < 8; j++) {
                uint32_t b0 = Bs[kq    ][wn + j * 8 + rq];
                uint32_t b1 = Bs[kq + 4][wn + j * 8 + rq];
                #pragma unroll
                for (int i = 0; i < 2; i++) {
                    asm volatile(
                        "mma.sync.aligned.m16n8k8.row.col.f32.tf32.tf32.f32 "
                        "{%0,%1,%2,%3}, {%4,%5,%6,%7}, {%8,%9}, {%0,%1,%2,%3};"
                        : "+f"(acc[i][j][0]), "+f"(acc[i][j][1]),
                          "+f"(acc[i][j][2]), "+f"(acc[i][j][3])
                        : "r"(a[i][0]), "r"(a[i][1]), "r"(a[i][2]), "r"(a[i][3]),
                          "r"(b0), "r"(b1));
                }
            }
        }
    }

    // Epilogue: c[0],c[1] -> row lane/4 ; c[2],c[3] -> row lane/4+8 ;
    // cols (lane%4)*2 + {0,1}
    const int rq = lane >> 2;
    const int cq = (lane & 3) * 2;
    #pragma unroll
    for (int i = 0; i < 2; i++) {
        #pragma unroll
        for (int half = 0; half < 2; half++) {
            int row = m0 + wm + i * 16 + rq + half * 8;
            #pragma unroll
            for (int j = 0; j < 8; j++) {
                int col = n0 + wn + j * 8 + cq;
                size_t off = (size_t)row * N + col;
                float v0 = acc[i][j][half * 2 + 0] + bias[col];
                float v1 = acc[i][j][half * 2 + 1] + bias[col + 1];
                if (ACT == 1) {
                    v0 = 0.5f * v0 * (1.0f + erff(v0 * 0.70710678118654752f));
                    v1 = 0.5f * v1 * (1.0f + erff(v1 * 0.70710678118654752f));
                }
                if (RES) {
                    float2 r = *(const float2*)&Res[off];
                    v0 += r.x; v1 += r.y;
                }
                *(float2*)&C[off] = make_float2(v0, v1);
            }
        }
    }
}

// ---------------------------------------------------------------------------
// Fused attention (flash style, fp32).  1 thread = 1 query row.
// ---------------------------------------------------------------------------
__global__ __launch_bounds__(128)
void attn_k(const float* __restrict__ qkv, float* __restrict__ out) {
    const int bh = blockIdx.y;
    const int b = bh >> 3, h = bh & 7;
    const int tid = threadIdx.x;
    const int q_row = blockIdx.x * 128 + tid;
    const float scale = 0.14433756729740643f;   // 48^-0.5
    const size_t base = (size_t)b * N_ * QKVC;

    float q[HD];
    {
        const float* qp = qkv + base + (size_t)q_row * QKVC + h * HD;
        #pragma unroll
        for (int d = 0; d < HD; d++) q[d] = qp[d] * scale;
    }
    float o[HD];
    #pragma unroll
    for (int d = 0; d < HD; d++) o[d] = 0.0f;
    float mmax = -1e30f, l = 0.0f;

    __shared__ float Ks[32][HD];
    __shared__ float Vs[32][HD];

    for (int kt = 0; kt < N_ / 32; kt++) {
        __syncthreads();
        for (int i = tid; i < 32 * HD; i += 128) {
            int r = i / HD, c = i % HD;
            const float* kp = qkv + base + (size_t)(kt * 32 + r) * QKVC;
            Ks[r][c] = kp[C_     + h * HD + c];
            Vs[r][c] = kp[2 * C_ + h * HD + c];
        }
        __syncthreads();

        float s[32];
        float mt = mmax;
        #pragma unroll
        for (int j = 0; j < 32; j++) {
            float acc = 0.0f;
            #pragma unroll
            for (int d = 0; d < HD; d++) acc += q[d] * Ks[j][d];
            s[j] = acc;
            mt = fmaxf(mt, acc);
        }
        float corr = __expf(mmax - mt);
        l *= corr;
        #pragma unroll
        for (int d = 0; d < HD; d++) o[d] *= corr;
        #pragma unroll
        for (int j = 0; j < 32; j++) {
            float p = __expf(s[j] - mt);
            l += p;
            #pragma unroll
            for (int d = 0; d < HD; d++) o[d] += p * Vs[j][d];
        }
        mmax = mt;
    }

    float inv = 1.0f / l;
    float* op = out + (size_t)(b * N_ + q_row) * C_ + h * HD;
    #pragma unroll
    for (int d = 0; d < HD; d++) op[d] = o[d] * inv;
}

// ---------------------------------------------------------------------------
// Launch
// ---------------------------------------------------------------------------
extern "C" void kernel_launch(void* const* d_in, const int* in_sizes, int n_in,
                              void* d_out, int out_size) {
    const float* x     = (const float*)d_in[0];
    const float* ln1w  = (const float*)d_in[1];
    const float* ln1b  = (const float*)d_in[2];
    const float* qkvw  = (const float*)d_in[3];
    const float* qkvb  = (const float*)d_in[4];
    const float* projw = (const float*)d_in[5];
    const float* projb = (const float*)d_in[6];
    const float* ln2w  = (const float*)d_in[7];
    const float* ln2b  = (const float*)d_in[8];
    const float* fc1w  = (const float*)d_in[9];
    const float* fc1b  = (const float*)d_in[10];
    const float* fc2w  = (const float*)d_in[11];
    const float* fc2b  = (const float*)d_in[12];

    float *xf, *h, *qkv, *att, *x2, *mid;
    cudaGetSymbolAddress((void**)&xf,  g_xf);
    cudaGetSymbolAddress((void**)&h,   g_h);
    cudaGetSymbolAddress((void**)&qkv, g_qkv);
    cudaGetSymbolAddress((void**)&att, g_att);
    cudaGetSymbolAddress((void**)&x2,  g_x2);
    cudaGetSymbolAddress((void**)&mid, g_mid);

    // 1. x (B,C,N) -> xf (B,N,C)
    transpose_k<<<dim3(N_/32, C_/32, B_), dim3(32, 32)>>>(x, xf, C_, N_);
    // 2. LN1
    ln_k<<<M_, 128>>>(xf, ln1w, ln1b, h);
    // 3. QKV projection
    gemm_tf32<0,0><<<dim3(QKVC/128, M_/128), 256>>>(h, qkvw, qkvb, nullptr, qkv, M_, QKVC, C_);
    // 4. attention
    attn_k<<<dim3(N_/128, B_*NH), 128>>>(qkv, att);
    // 5. proj + residual(xf) -> x2
    gemm_tf32<0,1><<<dim3(C_/128, M_/128), 256>>>(att, projw, projb, xf, x2, M_, C_, C_);
    // 6. LN2
    ln_k<<<M_, 128>>>(x2, ln2w, ln2b, h);
    // 7. fc1 + GELU
    gemm_tf32<1,0><<<dim3(HID/128, M_/128), 256>>>(h, fc1w, fc1b, nullptr, mid, M_, HID, C_);
    // 8. fc2 + residual(x2) -> y (in g_h)
    gemm_tf32<0,1><<<dim3(C_/128, M_/128), 256>>>(mid, fc2w, fc2b, x2, h, M_, C_, HID);
    // 9. y (B,N,C) -> out (B,C,N)
    transpose_k<<<dim3(C_/32, N_/32, B_), dim3(32, 32)>>>(h, (float*)d_out, N_, C_);
}

// round 4
// speedup vs baseline: 1.0019x; 1.0019x over previous
#include <cuda_runtime.h>
#include <math.h>
#include <stdint.h>

// Problem constants
#define B_   16
#define C_   384
#define N_   1024
#define NH   8
#define HD   48
#define HID  1536
#define M_   (B_*N_)     // 16384 tokens
#define QKVC (3*C_)      // 1152

// ---------------------------------------------------------------------------
// Scratch (static __device__ — no allocation allowed)
// ---------------------------------------------------------------------------
__device__ float g_xf [M_*C_];     // tokens (B,N,C)
__device__ float g_h  [M_*C_];     // LN output / final y (reused)
__device__ float g_qkv[M_*QKVC];   // qkv projections
__device__ float g_att[M_*C_];     // attention output
__device__ float g_x2 [M_*C_];     // residual after attention
__device__ float g_mid[M_*HID];    // FFN hidden

// ---------------------------------------------------------------------------
// Transpose: in (batch, rows, cols) -> out (batch, cols, rows)
// ---------------------------------------------------------------------------
__global__ void transpose_k(const float* __restrict__ in, float* __restrict__ out,
                            int rows, int cols) {
    __shared__ float t[32][33];
    int b = blockIdx.z;
    const float* ib = in  + (size_t)b * rows * cols;
    float*       ob = out + (size_t)b * rows * cols;
    int r = blockIdx.y * 32 + threadIdx.y;
    int c = blockIdx.x * 32 + threadIdx.x;
    t[threadIdx.y][threadIdx.x] = ib[(size_t)r * cols + c];
    __syncthreads();
    int oc = blockIdx.x * 32 + threadIdx.y;
    int orr = blockIdx.y * 32 + threadIdx.x;
    ob[(size_t)oc * rows + orr] = t[threadIdx.x][threadIdx.y];
}

// ---------------------------------------------------------------------------
// LayerNorm over rows of length 384.  grid: M_ blocks, block: 128 threads
// ---------------------------------------------------------------------------
__global__ void ln_k(const float* __restrict__ X, const float* __restrict__ w,
                     const float* __restrict__ bias, float* __restrict__ Y) {
    int row = blockIdx.x;
    int tid = threadIdx.x;
    const float* xr = X + (size_t)row * C_;
    float v0 = xr[tid], v1 = xr[tid + 128], v2 = xr[tid + 256];
    float s = v0 + v1 + v2;
    float q = v0 * v0 + v1 * v1 + v2 * v2;
    #pragma unroll
    for (int o = 16; o > 0; o >>= 1) {
        s += __shfl_xor_sync(0xffffffffu, s, o);
        q += __shfl_xor_sync(0xffffffffu, q, o);
    }
    __shared__ float ss[4], sq[4];
    int wid = tid >> 5, lane = tid & 31;
    if (lane == 0) { ss[wid] = s; sq[wid] = q; }
    __syncthreads();
    s = ss[0] + ss[1] + ss[2] + ss[3];
    q = sq[0] + sq[1] + sq[2] + sq[3];
    float mean = s * (1.0f / C_);
    float var  = q * (1.0f / C_) - mean * mean;
    float rstd = rsqrtf(var + 1e-5f);
    float* yr = Y + (size_t)row * C_;
    yr[tid]       = (v0 - mean) * rstd * w[tid]       + bias[tid];
    yr[tid + 128] = (v1 - mean) * rstd * w[tid + 128] + bias[tid + 128];
    yr[tid + 256] = (v2 - mean) * rstd * w[tid + 256] + bias[tid + 256];
}

// ---------------------------------------------------------------------------
// TF32 tensor-core NT GEMM: C[M,N] = A[M,K] * B[N,K]^T + bias[N]
// tile 128x128x32, 256 threads (8 warps, 4 in M x 2 in N), warp tile 32x64.
// mma.sync.aligned.m16n8k8 tf32. ACT: 1=exact GELU. RES: add residual.
// ---------------------------------------------------------------------------
__device__ __forceinline__ uint32_t f2tf32(float f) {
    uint32_t o;
    asm("cvt.rna.tf32.f32 %0, %1;" : "=r"(o) : "f"(f));
    return o;
}

#define AS_STRIDE 129

template<int ACT, int RES>
__global__ __launch_bounds__(256)
void gemm_tf32(const float* __restrict__ A, const float* __restrict__ B,
               const float* __restrict__ bias, const float* __restrict__ Res,
               float* __restrict__ C, int M, int N, int K) {
    __shared__ uint32_t As[32][AS_STRIDE];   // [k][m], tf32 bits
    __shared__ uint32_t Bs[32][AS_STRIDE];   // [k][n]

    const int tid  = threadIdx.x;
    const int lane = tid & 31;
    const int warp = tid >> 5;
    const int wm = (warp & 3) * 32;      // warp M offset in tile
    const int wn = (warp >> 2) * 64;     // warp N offset in tile
    const int m0 = blockIdx.y * 128;
    const int n0 = blockIdx.x * 128;

    float acc[2][8][4];
    #pragma unroll
    for (int i = 0; i < 2; i++)
        #pragma unroll
        for (int j = 0; j < 8; j++)
            #pragma unroll
            for (int c = 0; c < 4; c++) acc[i][j][c] = 0.0f;

    const int lr = tid >> 3;         // 0..31 : row within tile chunk
    const int lk = (tid & 7) * 4;    // k offset (float4)

    for (int k0 = 0; k0 < K; k0 += 32) {
        __syncthreads();
        #pragma unroll
        for (int hh = 0; hh < 4; hh++) {
            int r = lr + hh * 32;
            float4 va = *(const float4*)&A[(size_t)(m0 + r) * K + k0 + lk];
            As[lk + 0][r] = f2tf32(va.x); As[lk + 1][r] = f2tf32(va.y);
            As[lk + 2][r] = f2tf32(va.z); As[lk + 3][r] = f2tf32(va.w);
            float4 vb = *(const float4*)&B[(size_t)(n0 + r) * K + k0 + lk];
            Bs[lk + 0][r] = f2tf32(vb.x); Bs[lk + 1][r] = f2tf32(vb.y);
            Bs[lk + 2][r] = f2tf32(vb.z); Bs[lk + 3][r] = f2tf32(vb.w);
        }
        __syncthreads();

        #pragma unroll
        for (int kk = 0; kk < 32; kk += 8) {
            const int kq  = kk + (lane & 3);      // lane%4
            const int rq  = lane >> 2;            // lane/4
            uint32_t a[2][4];
            #pragma unroll
            for (int i = 0; i < 2; i++) {
                int rb = wm + i * 16 + rq;
                a[i][0] = As[kq    ][rb];
                a[i][1] = As[kq    ][rb + 8];
                a[i][2] = As[kq + 4][rb];
                a[i][3] = As[kq + 4][rb + 8];
            }
            #pragma unroll
            for (int j = 0; j < 8; j++) {
                uint32_t b0 = Bs[kq    ][wn + j * 8 + rq];
                uint32_t b1 = Bs[kq + 4][wn + j * 8 + rq];
                #pragma unroll
                for (int i = 0; i < 2; i++) {
                    asm volatile(
                        "mma.sync.aligned.m16n8k8.row.col.f32.tf32.tf32.f32 "
                        "{%0,%1,%2,%3}, {%4,%5,%6,%7}, {%8,%9}, {%0,%1,%2,%3};"
                        : "+f"(acc[i][j][0]), "+f"(acc[i][j][1]),
                          "+f"(acc[i][j][2]), "+f"(acc[i][j][3])
                        : "r"(a[i][0]), "r"(a[i][1]), "r"(a[i][2]), "r"(a[i][3]),
                          "r"(b0), "r"(b1));
                }
            }
        }
    }

    // Epilogue: c[0],c[1] -> row lane/4 ; c[2],c[3] -> row lane/4+8 ;
    // cols (lane%4)*2 + {0,1}
    const int rq = lane >> 2;
    const int cq = (lane & 3) * 2;
    #pragma unroll
    for (int i = 0; i < 2; i++) {
        #pragma unroll
        for (int half = 0; half < 2; half++) {
            int row = m0 + wm + i * 16 + rq + half * 8;
            #pragma unroll
            for (int j = 0; j < 8; j++) {
                int col = n0 + wn + j * 8 + cq;
                size_t off = (size_t)row * N + col;
                float v0 = acc[i][j][half * 2 + 0] + bias[col];
                float v1 = acc[i][j][half * 2 + 1] + bias[col + 1];
                if (ACT == 1) {
                    v0 = 0.5f * v0 * (1.0f + erff(v0 * 0.70710678118654752f));
                    v1 = 0.5f * v1 * (1.0f + erff(v1 * 0.70710678118654752f));
                }
                if (RES) {
                    float2 r = *(const float2*)&Res[off];
                    v0 += r.x; v1 += r.y;
                }
                *(float2*)&C[off] = make_float2(v0, v1);
            }
        }
    }
}

// ---------------------------------------------------------------------------
// Fused attention (flash style, fp32).  1 thread = 1 query row.
// ---------------------------------------------------------------------------
__global__ __launch_bounds__(128)
void attn_k(const float* __restrict__ qkv, float* __restrict__ out) {
    const int bh = blockIdx.y;
    const int b = bh >> 3, h = bh & 7;
    const int tid = threadIdx.x;
    const int q_row = blockIdx.x * 128 + tid;
    const float scale = 0.14433756729740643f;   // 48^-0.5
    const size_t base = (size_t)b * N_ * QKVC;

    float q[HD];
    {
        const float* qp = qkv + base + (size_t)q_row * QKVC + h * HD;
        #pragma unroll
        for (int d = 0; d < HD; d++) q[d] = qp[d] * scale;
    }
    float o[HD];
    #pragma unroll
    for (int d = 0; d < HD; d++) o[d] = 0.0f;
    float mmax = -1e30f, l = 0.0f;

    __shared__ float Ks[32][HD];
    __shared__ float Vs[32][HD];

    for (int kt = 0; kt < N_ / 32; kt++) {
        __syncthreads();
        for (int i = tid; i < 32 * HD; i += 128) {
            int r = i / HD, c = i % HD;
            const float* kp = qkv + base + (size_t)(kt * 32 + r) * QKVC;
            Ks[r][c] = kp[C_     + h * HD + c];
            Vs[r][c] = kp[2 * C_ + h * HD + c];
        }
        __syncthreads();

        float s[32];
        float mt = mmax;
        #pragma unroll
        for (int j = 0; j < 32; j++) {
            float acc = 0.0f;
            #pragma unroll
            for (int d = 0; d < HD; d++) acc += q[d] * Ks[j][d];
            s[j] = acc;
            mt = fmaxf(mt, acc);
        }
        float corr = __expf(mmax - mt);
        l *= corr;
        #pragma unroll
        for (int d = 0; d < HD; d++) o[d] *= corr;
        #pragma unroll
        for (int j = 0; j < 32; j++) {
            float p = __expf(s[j] - mt);
            l += p;
            #pragma unroll
            for (int d = 0; d < HD; d++) o[d] += p * Vs[j][d];
        }
        mmax = mt;
    }

    float inv = 1.0f / l;
    float* op = out + (size_t)(b * N_ + q_row) * C_ + h * HD;
    #pragma unroll
    for (int d = 0; d < HD; d++) op[d] = o[d] * inv;
}

// ---------------------------------------------------------------------------
// Launch
// ---------------------------------------------------------------------------
extern "C" void kernel_launch(void* const* d_in, const int* in_sizes, int n_in,
                              void* d_out, int out_size) {
    const float* x     = (const float*)d_in[0];
    const float* ln1w  = (const float*)d_in[1];
    const float* ln1b  = (const float*)d_in[2];
    const float* qkvw  = (const float*)d_in[3];
    const float* qkvb  = (const float*)d_in[4];
    const float* projw = (const float*)d_in[5];
    const float* projb = (const float*)d_in[6];
    const float* ln2w  = (const float*)d_in[7];
    const float* ln2b  = (const float*)d_in[8];
    const float* fc1w  = (const float*)d_in[9];
    const float* fc1b  = (const float*)d_in[10];
    const float* fc2w  = (const float*)d_in[11];
    const float* fc2b  = (const float*)d_in[12];

    float *xf, *h, *qkv, *att, *x2, *mid;
    cudaGetSymbolAddress((void**)&xf,  g_xf);
    cudaGetSymbolAddress((void**)&h,   g_h);
    cudaGetSymbolAddress((void**)&qkv, g_qkv);
    cudaGetSymbolAddress((void**)&att, g_att);
    cudaGetSymbolAddress((void**)&x2,  g_x2);
    cudaGetSymbolAddress((void**)&mid, g_mid);

    // 1. x (B,C,N) -> xf (B,N,C)
    transpose_k<<<dim3(N_/32, C_/32, B_), dim3(32, 32)>>>(x, xf, C_, N_);
    // 2. LN1
    ln_k<<<M_, 128>>>(xf, ln1w, ln1b, h);
    // 3. QKV projection
    gemm_tf32<0,0><<<dim3(QKVC/128, M_/128), 256>>>(h, qkvw, qkvb, nullptr, qkv, M_, QKVC, C_);
    // 4. attention
    attn_k<<<dim3(N_/128, B_*NH), 128>>>(qkv, att);
    // 5. proj + residual(xf) -> x2
    gemm_tf32<0,1><<<dim3(C_/128, M_/128), 256>>>(att, projw, projb, xf, x2, M_, C_, C_);
    // 6. LN2
    ln_k<<<M_, 128>>>(x2, ln2w, ln2b, h);
    // 7. fc1 + GELU
    gemm_tf32<1,0><<<dim3(HID/128, M_/128), 256>>>(h, fc1w, fc1b, nullptr, mid, M_, HID, C_);
    // 8. fc2 + residual(x2) -> y (in g_h)
    gemm_tf32<0,1><<<dim3(C_/128, M_/128), 256>>>(mid, fc2w, fc2b, x2, h, M_, C_, HID);
    // 9. y (B,N,C) -> out (B,C,N)
    transpose_k<<<dim3(C_/32, N_/32, B_), dim3(32, 32)>>>(h, (float*)d_out, N_, C_);
}